// round 2
// baseline (speedup 1.0000x reference)
#include <cuda_runtime.h>

#define TT 512
#define BB 256
#define II 64
#define HH 512
#define G3 1536
#define RT (TT*BB)

typedef unsigned long long u64;

__device__ float g_gi[(size_t)RT * G3];   // input projections
__device__ float g_Z [(size_t)RT * HH];   // hidden states
__device__ float g_h0[BB * HH];           // zeros (never written)

__device__ __forceinline__ u64 ffma2(u64 a, u64 b, u64 c){
    u64 d;
    asm("fma.rn.f32x2 %0, %1, %2, %3;" : "=l"(d) : "l"(a), "l"(b), "l"(c));
    return d;
}
__device__ __forceinline__ float pairsum(u64 v){
    float lo, hi;
    asm("mov.b64 {%0, %1}, %2;" : "=f"(lo), "=f"(hi) : "l"(v));
    return lo + hi;
}
__device__ __forceinline__ float sigf(float x){
    return __fdividef(1.0f, 1.0f + __expf(-x));
}

// ---------------- Phase 1: gi[r,c] = X[r,:] . Wih[c,:] + bih[c] ----------------
#define GIS 66
__global__ __launch_bounds__(256) void gi_kernel(const float* __restrict__ X,
                                                 const float* __restrict__ Wih,
                                                 const float* __restrict__ bih)
{
    __shared__ __align__(16) float Xs[64 * GIS];
    __shared__ __align__(16) float Ws[64 * GIS];
    const int r0 = blockIdx.x * 64;
    const int c0 = blockIdx.y * 64;
    const int t  = threadIdx.x;

    #pragma unroll
    for (int j = 0; j < 4; j++){
        int q   = t + 256 * j;
        int row = q >> 4;          // 0..63
        int kq  = q & 15;          // 0..15
        const u64* gx = reinterpret_cast<const u64*>(&X[(size_t)(r0+row)*II + kq*4]);
        u64* px = reinterpret_cast<u64*>(&Xs[row*GIS + kq*4]);
        px[0] = gx[0]; px[1] = gx[1];
        const u64* gw = reinterpret_cast<const u64*>(&Wih[(size_t)(c0+row)*II + kq*4]);
        u64* pw = reinterpret_cast<u64*>(&Ws[row*GIS + kq*4]);
        pw[0] = gw[0]; pw[1] = gw[1];
    }
    __syncthreads();

    const int tm = t & 15;         // rows tm+16i
    const int tn = t >> 4;         // cols tn+16j
    u64 acc[4][4];
    #pragma unroll
    for (int i = 0; i < 4; i++)
        #pragma unroll
        for (int j = 0; j < 4; j++) acc[i][j] = 0ull;

    #pragma unroll 8
    for (int k = 0; k < 64; k += 2){
        u64 a[4], b[4];
        #pragma unroll
        for (int i = 0; i < 4; i++)
            a[i] = *reinterpret_cast<const u64*>(&Xs[(tm+16*i)*GIS + k]);
        #pragma unroll
        for (int j = 0; j < 4; j++)
            b[j] = *reinterpret_cast<const u64*>(&Ws[(tn+16*j)*GIS + k]);
        #pragma unroll
        for (int i = 0; i < 4; i++)
            #pragma unroll
            for (int j = 0; j < 4; j++)
                acc[i][j] = ffma2(a[i], b[j], acc[i][j]);
    }

    #pragma unroll
    for (int i = 0; i < 4; i++){
        #pragma unroll
        for (int j = 0; j < 4; j++){
            int c = c0 + tn + 16*j;
            g_gi[(size_t)(r0 + tm + 16*i)*G3 + c] = pairsum(acc[i][j]) + bih[c];
        }
    }
}

// ---------------- Phase 2: one GRU step (fused gates) ----------------
#define KC 32
#define SS 34
__global__ __launch_bounds__(256) void step_kernel(int t,
                                                   const float* __restrict__ Whh,
                                                   const float* __restrict__ bhh)
{
    __shared__ __align__(16) float As[32 * SS];
    __shared__ __align__(16) float Bs[96 * SS];

    const float* hprev = (t == 0) ? g_h0 : (g_Z + (size_t)(t-1)*BB*HH);
    const float* git   = g_gi + (size_t)t * BB * G3;
    float*       hout  = g_Z  + (size_t)t * BB * HH;

    const int b0  = blockIdx.x * 32;
    const int h0  = blockIdx.y * 32;
    const int tid = threadIdx.x;

    const int am  = tid & 31;
    const int akq = tid >> 5;           // 0..7
    int brow[3], bkq[3], bnl[3];
    #pragma unroll
    for (int j = 0; j < 3; j++){
        int q  = tid + 256 * j;
        int n  = q % 96;
        bkq[j] = q / 96;                // 0..7
        bnl[j] = n;
        brow[j] = (n < 32) ? (h0 + n)
                : (n < 64) ? (HH   + h0 + (n - 32))
                           : (2*HH + h0 + (n - 64));
    }

    const int mq = tid & 7;             // batches mq+8i
    const int u  = tid >> 3;            // hidden unit 0..31

    u64 accr[4], accz[4], accn[4];
    #pragma unroll
    for (int i = 0; i < 4; i++){ accr[i]=0ull; accz[i]=0ull; accn[i]=0ull; }

    u64 sa0, sa1, sb[3][2];
    const int NCH = HH / KC;            // 16
    {
        const u64* g = reinterpret_cast<const u64*>(&hprev[(size_t)(b0+am)*HH + akq*4]);
        sa0 = g[0]; sa1 = g[1];
        #pragma unroll
        for (int j = 0; j < 3; j++){
            const u64* gb = reinterpret_cast<const u64*>(&Whh[(size_t)brow[j]*HH + bkq[j]*4]);
            sb[j][0] = gb[0]; sb[j][1] = gb[1];
        }
    }

    for (int c = 0; c < NCH; c++){
        {   // store staged chunk
            u64* pa = reinterpret_cast<u64*>(&As[am*SS + akq*4]);
            pa[0] = sa0; pa[1] = sa1;
            #pragma unroll
            for (int j = 0; j < 3; j++){
                u64* pb = reinterpret_cast<u64*>(&Bs[bnl[j]*SS + bkq[j]*4]);
                pb[0] = sb[j][0]; pb[1] = sb[j][1];
            }
        }
        __syncthreads();
        if (c < NCH-1){
            int k0 = (c+1) * KC;
            const u64* g = reinterpret_cast<const u64*>(&hprev[(size_t)(b0+am)*HH + k0 + akq*4]);
            sa0 = g[0]; sa1 = g[1];
            #pragma unroll
            for (int j = 0; j < 3; j++){
                const u64* gb = reinterpret_cast<const u64*>(&Whh[(size_t)brow[j]*HH + k0 + bkq[j]*4]);
                sb[j][0] = gb[0]; sb[j][1] = gb[1];
            }
        }
        #pragma unroll
        for (int k = 0; k < KC; k += 2){
            u64 br = *reinterpret_cast<const u64*>(&Bs[ u      *SS + k]);
            u64 bz = *reinterpret_cast<const u64*>(&Bs[(32+u)  *SS + k]);
            u64 bn = *reinterpret_cast<const u64*>(&Bs[(64+u)  *SS + k]);
            #pragma unroll
            for (int i = 0; i < 4; i++){
                u64 a = *reinterpret_cast<const u64*>(&As[(mq+8*i)*SS + k]);
                accr[i] = ffma2(a, br, accr[i]);
                accz[i] = ffma2(a, bz, accz[i]);
                accn[i] = ffma2(a, bn, accn[i]);
            }
        }
        __syncthreads();
    }

    const int jg  = h0 + u;
    const float bhr = bhh[jg], bhz = bhh[HH + jg], bhn = bhh[2*HH + jg];
    #pragma unroll
    for (int i = 0; i < 4; i++){
        int b = b0 + mq + 8*i;
        float pr = pairsum(accr[i]) + bhr;
        float pz = pairsum(accz[i]) + bhz;
        float pn = pairsum(accn[i]) + bhn;
        const float* g = git + (size_t)b * G3;
        float r  = sigf(g[jg] + pr);
        float z  = sigf(g[HH + jg] + pz);
        float nn = tanhf(g[2*HH + jg] + r * pn);
        float hp = hprev[(size_t)b*HH + jg];
        hout[(size_t)b*HH + jg] = (1.0f - z) * nn + z * hp;
    }
}

// ---------------- Phase 3: V = bias + Z . vw ----------------
__global__ __launch_bounds__(256) void value_kernel(const float* __restrict__ vw,
                                                    const float* __restrict__ bias,
                                                    float* __restrict__ out)
{
    int warp = (blockIdx.x * 256 + threadIdx.x) >> 5;
    int lane = threadIdx.x & 31;
    const float* z = g_Z + (size_t)warp * HH;
    float s = 0.0f;
    #pragma unroll
    for (int i = 0; i < 4; i++){
        int idx = i*128 + lane*4;
        float4 zv = *reinterpret_cast<const float4*>(&z[idx]);
        float4 wv = *reinterpret_cast<const float4*>(&vw[idx]);
        s += zv.x*wv.x + zv.y*wv.y + zv.z*wv.z + zv.w*wv.w;
    }
    #pragma unroll
    for (int o = 16; o > 0; o >>= 1)
        s += __shfl_xor_sync(0xFFFFFFFFu, s, o);
    if (lane == 0) out[warp] = s + bias[0];
}

extern "C" void kernel_launch(void* const* d_in, const int* in_sizes, int n_in,
                              void* d_out, int out_size)
{
    const float* X    = (const float*)d_in[0];
    const float* Wih  = (const float*)d_in[1];
    const float* Whh  = (const float*)d_in[2];
    const float* bih  = (const float*)d_in[3];
    const float* bhh  = (const float*)d_in[4];
    const float* vw   = (const float*)d_in[5];
    const float* bias = (const float*)d_in[6];
    float* out = (float*)d_out;

    dim3 ggi(RT/64, G3/64);
    gi_kernel<<<ggi, 256>>>(X, Wih, bih);

    dim3 gst(BB/32, HH/32);
    for (int t = 0; t < TT; t++)
        step_kernel<<<gst, 256>>>(t, Whh, bhh);

    value_kernel<<<RT/8, 256>>>(vw, bias, out);
}

// round 3
// speedup vs baseline: 2.0510x; 2.0510x over previous
#include <cuda_runtime.h>

#define TT 512
#define BB 256
#define II 64
#define HH 512
#define G3 1536
#define RT (TT*BB)
#define NCTA 128
#define KC 32
#define AS 36
#define NCH (HH/KC)

typedef unsigned long long u64;

__device__ float g_giT[(size_t)TT * G3 * BB];   // [t][gate*H+unit][batch]
__device__ float g_Z  [(size_t)RT * HH];        // [t][b][h]
__device__ float g_h0 [BB * HH];                // zeros
__device__ unsigned g_bar_count;
__device__ unsigned g_bar_gen;

__device__ __forceinline__ u64 ffma2(u64 a, u64 b, u64 c){
    u64 d;
    asm("fma.rn.f32x2 %0, %1, %2, %3;" : "=l"(d) : "l"(a), "l"(b), "l"(c));
    return d;
}
__device__ __forceinline__ float pairsum(u64 v){
    float lo, hi;
    asm("mov.b64 {%0, %1}, %2;" : "=f"(lo), "=f"(hi) : "l"(v));
    return lo + hi;
}
__device__ __forceinline__ float sigf(float x){
    return __fdividef(1.0f, 1.0f + __expf(-x));
}
__device__ __forceinline__ void cpa16(void* dst, const void* src){
    unsigned d = (unsigned)__cvta_generic_to_shared(dst);
    asm volatile("cp.async.ca.shared.global [%0], [%1], 16;" :: "r"(d), "l"(src));
}
__device__ __forceinline__ void cpa_commit(){ asm volatile("cp.async.commit_group;"); }
__device__ __forceinline__ void cpa_wait0 (){ asm volatile("cp.async.wait_group 0;"); }

// ---------------- Phase 1: giT[t][c][b] = X[t,b,:] . Wih[c,:] + bih[c] ----------------
#define GIS 66
__global__ __launch_bounds__(256) void gi_kernel(const float* __restrict__ X,
                                                 const float* __restrict__ Wih,
                                                 const float* __restrict__ bih)
{
    __shared__ __align__(16) float Xs[64 * GIS];
    __shared__ __align__(16) float Ws[64 * GIS];
    const int r0 = blockIdx.x * 64;
    const int c0 = blockIdx.y * 64;
    const int t  = threadIdx.x;

    #pragma unroll
    for (int j = 0; j < 4; j++){
        int q   = t + 256 * j;
        int row = q >> 4;
        int kq  = q & 15;
        const u64* gx = reinterpret_cast<const u64*>(&X[(size_t)(r0+row)*II + kq*4]);
        u64* px = reinterpret_cast<u64*>(&Xs[row*GIS + kq*4]);
        px[0] = gx[0]; px[1] = gx[1];
        const u64* gw = reinterpret_cast<const u64*>(&Wih[(size_t)(c0+row)*II + kq*4]);
        u64* pw = reinterpret_cast<u64*>(&Ws[row*GIS + kq*4]);
        pw[0] = gw[0]; pw[1] = gw[1];
    }
    __syncthreads();

    const int tm = t & 15;
    const int tn = t >> 4;
    u64 acc[4][4];
    #pragma unroll
    for (int i = 0; i < 4; i++)
        #pragma unroll
        for (int j = 0; j < 4; j++) acc[i][j] = 0ull;

    #pragma unroll 8
    for (int k = 0; k < 64; k += 2){
        u64 a[4], b[4];
        #pragma unroll
        for (int i = 0; i < 4; i++)
            a[i] = *reinterpret_cast<const u64*>(&Xs[(tm+16*i)*GIS + k]);
        #pragma unroll
        for (int j = 0; j < 4; j++)
            b[j] = *reinterpret_cast<const u64*>(&Ws[(tn+16*j)*GIS + k]);
        #pragma unroll
        for (int i = 0; i < 4; i++)
            #pragma unroll
            for (int j = 0; j < 4; j++)
                acc[i][j] = ffma2(a[i], b[j], acc[i][j]);
    }

    #pragma unroll
    for (int i = 0; i < 4; i++){
        #pragma unroll
        for (int j = 0; j < 4; j++){
            int c = c0 + tn + 16*j;
            int r = r0 + tm + 16*i;
            g_giT[((size_t)(r >> 8) * G3 + c) * BB + (r & 255)] = pairsum(acc[i][j]) + bih[c];
        }
    }
}

// ---------------- Phase 2: persistent GRU (all 512 steps, grid barrier) ----------------
__global__ __launch_bounds__(128, 1) void step_persist(const float* __restrict__ Whh,
                                                       const float* __restrict__ bhh)
{
    __shared__ __align__(16) float As[2][32 * AS];  // h chunk   [buf][b][k]
    __shared__ __align__(16) float Bs[2][96 * AS];  // Whh chunk [buf][gaterow][k]

    const int b0  = blockIdx.x * 32;     // gridDim.x = 8
    const int h0  = blockIdx.y * 32;     // gridDim.y = 16
    const int tid = threadIdx.x;
    const int mq  = tid & 7;             // batches b0 + mq + 8i
    const int u   = tid >> 3;            // units  h0 + u, h0 + u + 16

    // bias registers
    float bhr[2], bhz[2], bhn[2];
    #pragma unroll
    for (int j = 0; j < 2; j++){
        int jg = h0 + u + 16*j;
        bhr[j] = bhh[jg]; bhz[j] = bhh[HH + jg]; bhn[j] = bhh[2*HH + jg];
    }

    // precomputed B global rows for loading (6 float4 per thread per chunk)
    int bRowG[6], bRowS[6], bKq[6];
    #pragma unroll
    for (int jj = 0; jj < 6; jj++){
        int idx = tid + 128 * jj;        // 0..767
        int row = idx >> 3;              // 0..95
        bKq[jj]   = idx & 7;
        bRowS[jj] = row;
        bRowG[jj] = (row >> 5) * HH + h0 + (row & 31);   // row in Whh (1536 rows)
    }

    unsigned gen = 0;
    if (tid == 0)
        asm volatile("ld.acquire.gpu.u32 %0, [%1];" : "=r"(gen) : "l"(&g_bar_count) : "memory");
    // gen baseline from g_bar_gen (not count):
    if (tid == 0)
        asm volatile("ld.acquire.gpu.u32 %0, [%1];" : "=r"(gen) : "l"(&g_bar_gen) : "memory");

    for (int t = 0; t < TT; t++){
        const float* hprev = (t == 0) ? g_h0 : (g_Z + (size_t)(t-1)*BB*HH);
        float*       hout  = g_Z + (size_t)t * BB * HH;
        const float* git   = g_giT + (size_t)t * G3 * BB;

        // prologue: chunk 0 -> buf 0
        #pragma unroll
        for (int jj = 0; jj < 2; jj++){
            int idx = tid + 128*jj, row = idx >> 3, kq = idx & 7;
            cpa16(&As[0][row*AS + kq*4], &hprev[(size_t)(b0+row)*HH + kq*4]);
        }
        #pragma unroll
        for (int jj = 0; jj < 6; jj++)
            cpa16(&Bs[0][bRowS[jj]*AS + bKq[jj]*4], &Whh[(size_t)bRowG[jj]*HH + bKq[jj]*4]);
        cpa_commit();

        u64 accr[2][4], accz[2][4], accn[2][4];
        #pragma unroll
        for (int j = 0; j < 2; j++)
            #pragma unroll
            for (int i = 0; i < 4; i++){ accr[j][i]=0ull; accz[j][i]=0ull; accn[j][i]=0ull; }

        for (int c = 0; c < NCH; c++){
            const int buf = c & 1;
            cpa_wait0();
            __syncthreads();
            if (c < NCH-1){
                const int nb = buf ^ 1, k0 = (c+1)*KC;
                #pragma unroll
                for (int jj = 0; jj < 2; jj++){
                    int idx = tid + 128*jj, row = idx >> 3, kq = idx & 7;
                    cpa16(&As[nb][row*AS + kq*4], &hprev[(size_t)(b0+row)*HH + k0 + kq*4]);
                }
                #pragma unroll
                for (int jj = 0; jj < 6; jj++)
                    cpa16(&Bs[nb][bRowS[jj]*AS + bKq[jj]*4], &Whh[(size_t)bRowG[jj]*HH + k0 + bKq[jj]*4]);
                cpa_commit();
            }
            #pragma unroll
            for (int k = 0; k < KC; k += 2){
                u64 a[4];
                #pragma unroll
                for (int i = 0; i < 4; i++)
                    a[i] = *reinterpret_cast<const u64*>(&As[buf][(mq+8*i)*AS + k]);
                #pragma unroll
                for (int j = 0; j < 2; j++){
                    int ur = u + 16*j;
                    u64 br = *reinterpret_cast<const u64*>(&Bs[buf][(     ur)*AS + k]);
                    u64 bz = *reinterpret_cast<const u64*>(&Bs[buf][(32 + ur)*AS + k]);
                    u64 bn = *reinterpret_cast<const u64*>(&Bs[buf][(64 + ur)*AS + k]);
                    #pragma unroll
                    for (int i = 0; i < 4; i++){
                        accr[j][i] = ffma2(a[i], br, accr[j][i]);
                        accz[j][i] = ffma2(a[i], bz, accz[j][i]);
                        accn[j][i] = ffma2(a[i], bn, accn[j][i]);
                    }
                }
            }
            __syncthreads();
        }

        // epilogue: fused gates
        #pragma unroll
        for (int j = 0; j < 2; j++){
            int jg = h0 + u + 16*j;
            #pragma unroll
            for (int i = 0; i < 4; i++){
                int b = b0 + mq + 8*i;
                float pr = pairsum(accr[j][i]) + bhr[j];
                float pz = pairsum(accz[j][i]) + bhz[j];
                float pn = pairsum(accn[j][i]) + bhn[j];
                float gir = git[(size_t)(        jg)*BB + b];
                float giz = git[(size_t)(HH   + jg)*BB + b];
                float gin = git[(size_t)(2*HH + jg)*BB + b];
                float r  = sigf(gir + pr);
                float z  = sigf(giz + pz);
                float nn = tanhf(gin + r * pn);
                float hp = hprev[(size_t)b*HH + jg];
                hout[(size_t)b*HH + jg] = (1.0f - z) * nn + z * hp;
            }
        }

        // grid barrier
        __syncthreads();
        if (tid == 0){
            __threadfence();
            unsigned arr = atomicAdd(&g_bar_count, 1);
            if (arr == NCTA - 1){
                atomicExch(&g_bar_count, 0);
                __threadfence();
                atomicAdd(&g_bar_gen, 1);
            } else {
                unsigned g;
                do {
                    asm volatile("ld.acquire.gpu.u32 %0, [%1];" : "=r"(g) : "l"(&g_bar_gen) : "memory");
                } while (g == gen);
            }
            gen++;
        }
        __syncthreads();
    }
}

// ---------------- Phase 3: V = bias + Z . vw ----------------
__global__ __launch_bounds__(256) void value_kernel(const float* __restrict__ vw,
                                                    const float* __restrict__ bias,
                                                    float* __restrict__ out)
{
    int warp = (blockIdx.x * 256 + threadIdx.x) >> 5;
    int lane = threadIdx.x & 31;
    const float* z = g_Z + (size_t)warp * HH;
    float s = 0.0f;
    #pragma unroll
    for (int i = 0; i < 4; i++){
        int idx = i*128 + lane*4;
        float4 zv = *reinterpret_cast<const float4*>(&z[idx]);
        float4 wv = *reinterpret_cast<const float4*>(&vw[idx]);
        s += zv.x*wv.x + zv.y*wv.y + zv.z*wv.z + zv.w*wv.w;
    }
    #pragma unroll
    for (int o = 16; o > 0; o >>= 1)
        s += __shfl_xor_sync(0xFFFFFFFFu, s, o);
    if (lane == 0) out[warp] = s + bias[0];
}

extern "C" void kernel_launch(void* const* d_in, const int* in_sizes, int n_in,
                              void* d_out, int out_size)
{
    const float* X    = (const float*)d_in[0];
    const float* Wih  = (const float*)d_in[1];
    const float* Whh  = (const float*)d_in[2];
    const float* bih  = (const float*)d_in[3];
    const float* bhh  = (const float*)d_in[4];
    const float* vw   = (const float*)d_in[5];
    const float* bias = (const float*)d_in[6];
    float* out = (float*)d_out;

    dim3 ggi(RT/64, G3/64);
    gi_kernel<<<ggi, 256>>>(X, Wih, bih);

    dim3 gst(BB/32, HH/32);   // 8 x 16 = 128 CTAs, all resident
    step_persist<<<gst, 128>>>(Whh, bhh);

    value_kernel<<<RT/8, 256>>>(vw, bias, out);
}